// round 1
// baseline (speedup 1.0000x reference)
#include <cuda_runtime.h>
#include <math.h>

// Problem geometry
#define HW_  2048
#define HOUT 2046            // VALID 3x3 conv output dim
#define NTOT (HW_ * HW_)     // 4194304

// Tiling: block 32x8 threads, each thread handles 2 output rows -> 32x16 tile
#define TW 32
#define TH 16
#define SW 34                // TW + 2 halo
#define SH 18                // TH + 2 halo

#define GX 64                // ceil(2046/32)
#define GY 128               // ceil(2046/16)
#define NBLK (GX * GY)       // 8192
#define CHUNK (NTOT / NBLK)  // 512 (exact)

__device__ float g_partials[3 * NBLK];

__device__ __forceinline__ float warp_sum(float x) {
#pragma unroll
    for (int o = 16; o > 0; o >>= 1) x += __shfl_down_sync(0xffffffffu, x, o);
    return x;
}

__global__ __launch_bounds__(256)
void stress_loss_kernel(const float* __restrict__ pred_E,
                        const float* __restrict__ pred_v,
                        const float* __restrict__ strain) {
    __shared__ float sE [SH][SW];
    __shared__ float sxx[SH][SW];
    __shared__ float syy[SH][SW];
    __shared__ float sxy[SH][SW];

    const int tx  = threadIdx.x;          // 0..31
    const int ty  = threadIdx.y;          // 0..7 (= warp id)
    const int tid = ty * 32 + tx;
    const int c0  = blockIdx.x * TW;
    const int r0  = blockIdx.y * TH;
    const int bid = blockIdx.y * gridDim.x + blockIdx.x;

    // ---- load halo tile, computing plane-stress on the fly ----
#pragma unroll
    for (int h = tid; h < SH * SW; h += 256) {
        const int hr = h / SW;
        const int hc = h - hr * SW;
        const int gr = r0 + hr;
        const int gc = c0 + hc;
        float E = 0.f, xx = 0.f, yy = 0.f, xy = 0.f;
        if (gr < HW_ && gc < HW_) {
            const long idx = (long)gr * HW_ + gc;
            E = pred_E[idx];
            const float v  = pred_v[idx];
            const float e0 = strain[3 * idx + 0];
            const float e1 = strain[3 * idx + 1];
            const float e2 = strain[3 * idx + 2];
            const float frac = E / (1.0f - v * v);
            xx = (e0 + v * e1) * frac;
            yy = (v * e0 + e1) * frac;
            xy = e2 * (1.0f - v) * 0.5f * frac;
        }
        sE [hr][hc] = E;
        sxx[hr][hc] = xx;
        syy[hr][hc] = yy;
        sxy[hr][hc] = xy;
    }
    __syncthreads();

    // ---- 3x3 stencil on the interior ----
    float sx_acc = 0.f, sy_acc = 0.f;
#pragma unroll
    for (int p = 0; p < 2; p++) {
        const int lr = ty + p * 8;        // local output row in tile (0..15)
        const int gr = r0 + lr;
        const int gc = c0 + tx;
        if (gr < HOUT && gc < HOUT) {
            // E_conv: 3x3 box sum
            float Ec = 0.f;
#pragma unroll
            for (int di = 0; di < 3; di++) {
                Ec += sE[lr + di][tx] + sE[lr + di][tx + 1] + sE[lr + di][tx + 2];
            }
            // sxy column/row sums (shared by fx and fy)
            const float sxy_c0 = sxy[lr][tx]     + sxy[lr + 1][tx]     + sxy[lr + 2][tx];
            const float sxy_c2 = sxy[lr][tx + 2] + sxy[lr + 1][tx + 2] + sxy[lr + 2][tx + 2];
            const float sxy_r0 = sxy[lr][tx]     + sxy[lr][tx + 1]     + sxy[lr][tx + 2];
            const float sxy_r2 = sxy[lr + 2][tx] + sxy[lr + 2][tx + 1] + sxy[lr + 2][tx + 2];

            // fx = conv(sxx, wx_xx) + conv(sxy, wx_xy)
            //    = rowsum(sxx,i+2) - rowsum(sxx,i) + colsum(sxy,j) - colsum(sxy,j+2)
            const float fx =
                (sxx[lr + 2][tx] + sxx[lr + 2][tx + 1] + sxx[lr + 2][tx + 2])
              - (sxx[lr][tx]     + sxx[lr][tx + 1]     + sxx[lr][tx + 2])
              + sxy_c0 - sxy_c2;

            // fy = conv(syy, wx_xy) + conv(sxy, wx_xx)
            const float fy =
                (syy[lr][tx]     + syy[lr + 1][tx]     + syy[lr + 2][tx])
              - (syy[lr][tx + 2] + syy[lr + 1][tx + 2] + syy[lr + 2][tx + 2])
              + sxy_r2 - sxy_r0;

            const float inv = 1.0f / Ec;
            sx_acc += fabsf(fx * inv);
            sy_acc += fabsf(fy * inv);
        }
    }

    // ---- mean(pred_E) contribution: exact contiguous chunk per block ----
    float se_acc = 0.f;
    {
        const int base = bid * CHUNK;
#pragma unroll
        for (int t = tid; t < CHUNK; t += 256) {
            se_acc += pred_E[base + t];
        }
    }

    // ---- block reduction (deterministic: fixed shuffle + loop order) ----
    sx_acc = warp_sum(sx_acc);
    sy_acc = warp_sum(sy_acc);
    se_acc = warp_sum(se_acc);

    __shared__ float red[3][8];
    if (tx == 0) {
        red[0][ty] = sx_acc;
        red[1][ty] = sy_acc;
        red[2][ty] = se_acc;
    }
    __syncthreads();
    if (tid == 0) {
        float ax = 0.f, ay = 0.f, ae = 0.f;
#pragma unroll
        for (int w = 0; w < 8; w++) { ax += red[0][w]; ay += red[1][w]; ae += red[2][w]; }
        g_partials[bid]            = ax;
        g_partials[NBLK + bid]     = ay;
        g_partials[2 * NBLK + bid] = ae;
    }
}

__global__ __launch_bounds__(256)
void finalize_kernel(float* __restrict__ out) {
    const int t = threadIdx.x;
    double ax = 0.0, ay = 0.0, ae = 0.0;
    for (int i = t; i < NBLK; i += 256) {
        ax += (double)g_partials[i];
        ay += (double)g_partials[NBLK + i];
        ae += (double)g_partials[2 * NBLK + i];
    }
    __shared__ double sax[256], say[256], sae[256];
    sax[t] = ax; say[t] = ay; sae[t] = ae;
    __syncthreads();
    for (int s = 128; s > 0; s >>= 1) {
        if (t < s) { sax[t] += sax[t + s]; say[t] += say[t + s]; sae[t] += sae[t + s]; }
        __syncthreads();
    }
    if (t == 0) {
        const double M = (double)HOUT * (double)HOUT;
        const double loss = sax[0] / M + say[0] / M
                          + fabs(sae[0] / (double)NTOT - 1.0) / 100.0;
        out[0] = (float)loss;
    }
}

extern "C" void kernel_launch(void* const* d_in, const int* in_sizes, int n_in,
                              void* d_out, int out_size) {
    const float* pred_E = (const float*)d_in[0];
    const float* pred_v = (const float*)d_in[1];
    const float* strain = (const float*)d_in[2];
    float* out = (float*)d_out;

    dim3 block(32, 8, 1);
    dim3 grid(GX, GY, 1);
    stress_loss_kernel<<<grid, block>>>(pred_E, pred_v, strain);
    finalize_kernel<<<1, 256>>>(out);
}

// round 3
// speedup vs baseline: 1.4464x; 1.4464x over previous
#include <cuda_runtime.h>
#include <math.h>

// ---------------- geometry ----------------
#define W_    2048
#define HOUT  2046                 // VALID 3x3 output dim
#define NTOT  (W_ * W_)

// warp-strip decomposition: warp = 128 input cols (124 owned outputs, 4-col
// overlap keeps float4 bases 16B-aligned) x R_OUT output rows
#define COLS_OUT 124
#define R_OUT  15
#define STRIPS 17                  // ceil(2046/124)
#define BANDS  137                 // ceil(2046/15)
#define NWARPS (STRIPS * BANDS)    // 2329
#define WPB    8                   // warps per block (256 threads)
#define NBLOCKS ((NWARPS + WPB - 1) / WPB)  // 292

__device__ float g_part[3 * NWARPS];

struct RowState {
    float hE[4];    // horizontal 3-sum of E, centered at each of the 4 cols
    float hXX[4];   // horizontal 3-sum of sxx
    float hXY[4];   // horizontal 3-sum of sxy
    float syy[4];   // raw syy
    float sxy[4];   // raw sxy
};

__device__ __forceinline__ float warp_sum(float x) {
#pragma unroll
    for (int o = 16; o > 0; o >>= 1) x += __shfl_down_sync(0xffffffffu, x, o);
    return x;
}

__device__ __forceinline__ void process_row(
    int r, int c0, bool colok, int own_hi_c, bool ownrow,
    const float* __restrict__ pE, const float* __restrict__ pv,
    const float* __restrict__ ps, RowState& out, float& accE)
{
    float E[4], v[4], e0[4], e1[4], e2[4];
    const int base = r * W_ + c0;   // c0 is a multiple of 4 -> 16B-aligned
    if (colok) {
        const float4 E4 = *reinterpret_cast<const float4*>(pE + base);
        const float4 v4 = *reinterpret_cast<const float4*>(pv + base);
        const float4* sp = reinterpret_cast<const float4*>(ps + 3 * base);
        const float4 a = sp[0];
        const float4 b = sp[1];
        const float4 c = sp[2];
        E[0] = E4.x; E[1] = E4.y; E[2] = E4.z; E[3] = E4.w;
        v[0] = v4.x; v[1] = v4.y; v[2] = v4.z; v[3] = v4.w;
        e0[0] = a.x; e1[0] = a.y; e2[0] = a.z;
        e0[1] = a.w; e1[1] = b.x; e2[1] = b.y;
        e0[2] = b.z; e1[2] = b.w; e2[2] = c.x;
        e0[3] = c.y; e1[3] = c.z; e2[3] = c.w;
    } else {
#pragma unroll
        for (int k = 0; k < 4; k++) { E[k] = 0.f; v[k] = 0.f; e0[k] = 0.f; e1[k] = 0.f; e2[k] = 0.f; }
    }

    float xx[4], xy[4];
#pragma unroll
    for (int k = 0; k < 4; k++) {
        const float frac = E[k] / (1.0f - v[k] * v[k]);
        xx[k]      = (e0[k] + v[k] * e1[k]) * frac;
        out.syy[k] = (v[k] * e0[k] + e1[k]) * frac;
        xy[k]      = e2[k] * (1.0f - v[k]) * 0.5f * frac;
        out.sxy[k] = xy[k];
    }

    // horizontal 3-sums via neighbor-lane exchange
    const float El = __shfl_up_sync  (0xffffffffu, E[3],  1);
    const float Er = __shfl_down_sync(0xffffffffu, E[0],  1);
    const float xl = __shfl_up_sync  (0xffffffffu, xx[3], 1);
    const float xr = __shfl_down_sync(0xffffffffu, xx[0], 1);
    const float yl = __shfl_up_sync  (0xffffffffu, xy[3], 1);
    const float yr = __shfl_down_sync(0xffffffffu, xy[0], 1);

    out.hE[0]  = El + E[0] + E[1];
    out.hE[1]  = E[0] + E[1] + E[2];
    out.hE[2]  = E[1] + E[2] + E[3];
    out.hE[3]  = E[2] + E[3] + Er;
    out.hXX[0] = xl + xx[0] + xx[1];
    out.hXX[1] = xx[0] + xx[1] + xx[2];
    out.hXX[2] = xx[1] + xx[2] + xx[3];
    out.hXX[3] = xx[2] + xx[3] + xr;
    out.hXY[0] = yl + xy[0] + xy[1];
    out.hXY[1] = xy[0] + xy[1] + xy[2];
    out.hXY[2] = xy[1] + xy[2] + xy[3];
    out.hXY[3] = xy[2] + xy[3] + yr;

    // mean(E): each pixel owned by exactly one warp
    if (ownrow) {
#pragma unroll
        for (int k = 0; k < 4; k++)
            if (c0 + k >= own_hi_c - COLS_OUT && c0 + k < own_hi_c) accE += E[k];
    }
}

__global__ __launch_bounds__(256, 2)
void stress_loss_kernel(const float* __restrict__ pE,
                        const float* __restrict__ pv,
                        const float* __restrict__ ps)
{
    const int w    = blockIdx.x * WPB + (threadIdx.x >> 5);
    const int lane = threadIdx.x & 31;
    float accx = 0.f, accy = 0.f, accE = 0.f;

    if (w < NWARPS) {
        const int strip = w / BANDS;
        const int band  = w - strip * BANDS;
        const int cb = strip * COLS_OUT;
        const int r0 = band * R_OUT;
        const int rows_out = min(R_OUT, HOUT - r0);
        const int c0 = cb + lane * 4;            // multiple of 4 -> aligned
        const bool colok = (c0 + 3 < W_);
        // ownership for mean(E): strip owns cols [cb, cb+124), last strip [cb, W_)
        const int own_hi_c = (strip == STRIPS - 1) ? W_ : cb + COLS_OUT;
        const int own_hi_r = (band  == BANDS  - 1) ? W_ : r0 + R_OUT;
        const int lk = lane * 4;

        RowState A, B, C;
        process_row(r0,     c0, colok, own_hi_c, (r0     < own_hi_r), pE, pv, ps, A, accE);
        process_row(r0 + 1, c0, colok, own_hi_c, (r0 + 1 < own_hi_r), pE, pv, ps, B, accE);

#pragma unroll 3
        for (int i = 0; i < rows_out; i++) {
            const int r = r0 + i + 2;
            process_row(r, c0, colok, own_hi_c, (r < own_hi_r), pE, pv, ps, C, accE);

            float vxy[4], vyy[4], Ec[4];
#pragma unroll
            for (int k = 0; k < 4; k++) {
                vxy[k] = A.sxy[k] + B.sxy[k] + C.sxy[k];
                vyy[k] = A.syy[k] + B.syy[k] + C.syy[k];
                Ec[k]  = A.hE[k]  + B.hE[k]  + C.hE[k];
            }
            const float vxyl = __shfl_up_sync  (0xffffffffu, vxy[3], 1);
            const float vxyr = __shfl_down_sync(0xffffffffu, vxy[0], 1);
            const float vyyl = __shfl_up_sync  (0xffffffffu, vyy[3], 1);
            const float vyyr = __shfl_down_sync(0xffffffffu, vyy[0], 1);

            const float dxy[4] = { vxyl - vxy[1], vxy[0] - vxy[2], vxy[1] - vxy[3], vxy[2] - vxyr };
            const float dyy[4] = { vyyl - vyy[1], vyy[0] - vyy[2], vyy[1] - vyy[3], vyy[2] - vyyr };

#pragma unroll
            for (int k = 0; k < 4; k++) {
                const int p = lk + k;                 // position within 128-col strip
                const int j = c0 + k - 1;             // global output column
                // strip owns outputs p in [1, 1+COLS_OUT)
                if (p >= 1 && p < 1 + COLS_OUT && j < HOUT) {
                    const float fx = C.hXX[k] - A.hXX[k] + dxy[k];
                    const float fy = dyy[k] + C.hXY[k] - A.hXY[k];
                    const float inv = 1.0f / Ec[k];
                    accx += fabsf(fx * inv);
                    accy += fabsf(fy * inv);
                }
            }
            A = B; B = C;
        }
    }

    accx = warp_sum(accx);
    accy = warp_sum(accy);
    accE = warp_sum(accE);
    if (lane == 0 && w < NWARPS) {
        g_part[w]              = accx;
        g_part[NWARPS + w]     = accy;
        g_part[2 * NWARPS + w] = accE;
    }
}

__global__ __launch_bounds__(256)
void finalize_kernel(float* __restrict__ out)
{
    const int t = threadIdx.x;
    double ax = 0.0, ay = 0.0, ae = 0.0;
    for (int i = t; i < NWARPS; i += 256) {
        ax += (double)g_part[i];
        ay += (double)g_part[NWARPS + i];
        ae += (double)g_part[2 * NWARPS + i];
    }
    __shared__ double sax[256], say[256], sae[256];
    sax[t] = ax; say[t] = ay; sae[t] = ae;
    __syncthreads();
    for (int s = 128; s > 0; s >>= 1) {
        if (t < s) { sax[t] += sax[t + s]; say[t] += say[t + s]; sae[t] += sae[t + s]; }
        __syncthreads();
    }
    if (t == 0) {
        const double M = (double)HOUT * (double)HOUT;
        out[0] = (float)(sax[0] / M + say[0] / M
                         + fabs(sae[0] / (double)NTOT - 1.0) / 100.0);
    }
}

extern "C" void kernel_launch(void* const* d_in, const int* in_sizes, int n_in,
                              void* d_out, int out_size)
{
    const float* pred_E = (const float*)d_in[0];
    const float* pred_v = (const float*)d_in[1];
    const float* strain = (const float*)d_in[2];
    float* out = (float*)d_out;

    stress_loss_kernel<<<NBLOCKS, 256>>>(pred_E, pred_v, strain);
    finalize_kernel<<<1, 256>>>(out);
}

// round 4
// speedup vs baseline: 2.3444x; 1.6208x over previous
#include <cuda_runtime.h>
#include <math.h>

// ---------------- geometry ----------------
#define W_    2048
#define HOUT  2046                 // VALID 3x3 output dim
#define NTOT  (W_ * W_)

// warp-strip decomposition: warp = 128 input cols (124 owned outputs, 4-col
// overlap keeps float4 bases 16B-aligned) x R_OUT output rows
#define COLS_OUT 124
#define R_OUT  15
#define STRIPS 17                  // ceil(2046/124)
#define BANDS  137                 // ceil(2046/15)
#define NWARPS (STRIPS * BANDS)    // 2329
#define WPB    8                   // warps per block (256 threads)
#define NBLOCKS ((NWARPS + WPB - 1) / WPB)  // 292

__device__ float g_bpart[3 * NBLOCKS];
__device__ unsigned int g_count;   // zero at module load; reset by last block

struct RowState {
    float hE[4];    // horizontal 3-sum of E, centered at each of the 4 cols
    float hXX[4];   // horizontal 3-sum of sxx
    float hXY[4];   // horizontal 3-sum of sxy
    float syy[4];   // raw syy
    float sxy[4];   // raw sxy
};

__device__ __forceinline__ float warp_sum(float x) {
#pragma unroll
    for (int o = 16; o > 0; o >>= 1) x += __shfl_down_sync(0xffffffffu, x, o);
    return x;
}

__device__ __forceinline__ void process_row(
    int r, int c0, bool colok, int own_hi_c, bool ownrow,
    const float* __restrict__ pE, const float* __restrict__ pv,
    const float* __restrict__ ps, RowState& out, float& accE)
{
    float E[4], v[4], e0[4], e1[4], e2[4];
    const int base = r * W_ + c0;   // c0 is a multiple of 4 -> 16B-aligned
    if (colok) {
        const float4 E4 = *reinterpret_cast<const float4*>(pE + base);
        const float4 v4 = *reinterpret_cast<const float4*>(pv + base);
        const float4* sp = reinterpret_cast<const float4*>(ps + 3 * base);
        const float4 a = sp[0];
        const float4 b = sp[1];
        const float4 c = sp[2];
        E[0] = E4.x; E[1] = E4.y; E[2] = E4.z; E[3] = E4.w;
        v[0] = v4.x; v[1] = v4.y; v[2] = v4.z; v[3] = v4.w;
        e0[0] = a.x; e1[0] = a.y; e2[0] = a.z;
        e0[1] = a.w; e1[1] = b.x; e2[1] = b.y;
        e0[2] = b.z; e1[2] = b.w; e2[2] = c.x;
        e0[3] = c.y; e1[3] = c.z; e2[3] = c.w;
    } else {
#pragma unroll
        for (int k = 0; k < 4; k++) { E[k] = 0.f; v[k] = 0.f; e0[k] = 0.f; e1[k] = 0.f; e2[k] = 0.f; }
    }

    float xx[4], xy[4];
#pragma unroll
    for (int k = 0; k < 4; k++) {
        const float frac = __fdividef(E[k], 1.0f - v[k] * v[k]);
        xx[k]      = (e0[k] + v[k] * e1[k]) * frac;
        out.syy[k] = (v[k] * e0[k] + e1[k]) * frac;
        xy[k]      = e2[k] * (1.0f - v[k]) * 0.5f * frac;
        out.sxy[k] = xy[k];
    }

    // horizontal 3-sums via neighbor-lane exchange
    const float El = __shfl_up_sync  (0xffffffffu, E[3],  1);
    const float Er = __shfl_down_sync(0xffffffffu, E[0],  1);
    const float xl = __shfl_up_sync  (0xffffffffu, xx[3], 1);
    const float xr = __shfl_down_sync(0xffffffffu, xx[0], 1);
    const float yl = __shfl_up_sync  (0xffffffffu, xy[3], 1);
    const float yr = __shfl_down_sync(0xffffffffu, xy[0], 1);

    out.hE[0]  = El + E[0] + E[1];
    out.hE[1]  = E[0] + E[1] + E[2];
    out.hE[2]  = E[1] + E[2] + E[3];
    out.hE[3]  = E[2] + E[3] + Er;
    out.hXX[0] = xl + xx[0] + xx[1];
    out.hXX[1] = xx[0] + xx[1] + xx[2];
    out.hXX[2] = xx[1] + xx[2] + xx[3];
    out.hXX[3] = xx[2] + xx[3] + xr;
    out.hXY[0] = yl + xy[0] + xy[1];
    out.hXY[1] = xy[0] + xy[1] + xy[2];
    out.hXY[2] = xy[1] + xy[2] + xy[3];
    out.hXY[3] = xy[2] + xy[3] + yr;

    // mean(E): each pixel owned by exactly one warp
    if (ownrow) {
#pragma unroll
        for (int k = 0; k < 4; k++)
            if (c0 + k >= own_hi_c - COLS_OUT && c0 + k < own_hi_c) accE += E[k];
    }
}

__global__ __launch_bounds__(256, 2)
void stress_loss_kernel(const float* __restrict__ pE,
                        const float* __restrict__ pv,
                        const float* __restrict__ ps,
                        float* __restrict__ out)
{
    const int wl   = threadIdx.x >> 5;
    const int w    = blockIdx.x * WPB + wl;
    const int lane = threadIdx.x & 31;
    const int tid  = threadIdx.x;
    float accx = 0.f, accy = 0.f, accE = 0.f;

    if (w < NWARPS) {
        const int strip = w / BANDS;
        const int band  = w - strip * BANDS;
        const int cb = strip * COLS_OUT;
        const int r0 = band * R_OUT;
        const int rows_out = min(R_OUT, HOUT - r0);
        const int c0 = cb + lane * 4;            // multiple of 4 -> aligned
        const bool colok = (c0 + 3 < W_);
        const int own_hi_c = (strip == STRIPS - 1) ? W_ : cb + COLS_OUT;
        const int own_hi_r = (band  == BANDS  - 1) ? W_ : r0 + R_OUT;
        const int lk = lane * 4;

        RowState A, B, C;
        process_row(r0,     c0, colok, own_hi_c, (r0     < own_hi_r), pE, pv, ps, A, accE);
        process_row(r0 + 1, c0, colok, own_hi_c, (r0 + 1 < own_hi_r), pE, pv, ps, B, accE);

#pragma unroll 3
        for (int i = 0; i < rows_out; i++) {
            const int r = r0 + i + 2;
            process_row(r, c0, colok, own_hi_c, (r < own_hi_r), pE, pv, ps, C, accE);

            float vxy[4], vyy[4], Ec[4];
#pragma unroll
            for (int k = 0; k < 4; k++) {
                vxy[k] = A.sxy[k] + B.sxy[k] + C.sxy[k];
                vyy[k] = A.syy[k] + B.syy[k] + C.syy[k];
                Ec[k]  = A.hE[k]  + B.hE[k]  + C.hE[k];
            }
            const float vxyl = __shfl_up_sync  (0xffffffffu, vxy[3], 1);
            const float vxyr = __shfl_down_sync(0xffffffffu, vxy[0], 1);
            const float vyyl = __shfl_up_sync  (0xffffffffu, vyy[3], 1);
            const float vyyr = __shfl_down_sync(0xffffffffu, vyy[0], 1);

            const float dxy[4] = { vxyl - vxy[1], vxy[0] - vxy[2], vxy[1] - vxy[3], vxy[2] - vxyr };
            const float dyy[4] = { vyyl - vyy[1], vyy[0] - vyy[2], vyy[1] - vyy[3], vyy[2] - vyyr };

#pragma unroll
            for (int k = 0; k < 4; k++) {
                const int p = lk + k;                 // position within 128-col strip
                const int j = c0 + k - 1;             // global output column
                if (p >= 1 && p < 1 + COLS_OUT && j < HOUT) {
                    const float fx = C.hXX[k] - A.hXX[k] + dxy[k];
                    const float fy = dyy[k] + C.hXY[k] - A.hXY[k];
                    const float inv = __fdividef(1.0f, Ec[k]);
                    accx += fabsf(fx * inv);
                    accy += fabsf(fy * inv);
                }
            }
            A = B; B = C;
        }
    }

    // ---- block reduction ----
    accx = warp_sum(accx);
    accy = warp_sum(accy);
    accE = warp_sum(accE);

    __shared__ float red[3][WPB];
    __shared__ int isLast;
    if (lane == 0) {
        red[0][wl] = accx;
        red[1][wl] = accy;
        red[2][wl] = accE;
    }
    __syncthreads();
    if (tid == 0) {
        float ax = 0.f, ay = 0.f, ae = 0.f;
#pragma unroll
        for (int q = 0; q < WPB; q++) { ax += red[0][q]; ay += red[1][q]; ae += red[2][q]; }
        g_bpart[blockIdx.x]               = ax;
        g_bpart[NBLOCKS + blockIdx.x]     = ay;
        g_bpart[2 * NBLOCKS + blockIdx.x] = ae;
        __threadfence();
        const unsigned int old = atomicAdd(&g_count, 1u);
        isLast = (old == NBLOCKS - 1);
    }
    __syncthreads();

    // ---- last block finalizes (fixed-order sum -> deterministic) ----
    if (isLast) {
        volatile const float* vp = (volatile const float*)g_bpart;
        double ax = 0.0, ay = 0.0, ae = 0.0;
        for (int i = tid; i < NBLOCKS; i += 256) {
            ax += (double)vp[i];
            ay += (double)vp[NBLOCKS + i];
            ae += (double)vp[2 * NBLOCKS + i];
        }
        __shared__ double sax[256], say[256], sae[256];
        sax[tid] = ax; say[tid] = ay; sae[tid] = ae;
        __syncthreads();
        for (int s = 128; s > 0; s >>= 1) {
            if (tid < s) { sax[tid] += sax[tid + s]; say[tid] += say[tid + s]; sae[tid] += sae[tid + s]; }
            __syncthreads();
        }
        if (tid == 0) {
            const double M = (double)HOUT * (double)HOUT;
            out[0] = (float)(sax[0] / M + say[0] / M
                             + fabs(sae[0] / (double)NTOT - 1.0) / 100.0);
            g_count = 0;   // reset for next graph replay
        }
    }
}

extern "C" void kernel_launch(void* const* d_in, const int* in_sizes, int n_in,
                              void* d_out, int out_size)
{
    const float* pred_E = (const float*)d_in[0];
    const float* pred_v = (const float*)d_in[1];
    const float* strain = (const float*)d_in[2];
    float* out = (float*)d_out;

    stress_loss_kernel<<<NBLOCKS, 256>>>(pred_E, pred_v, strain, out);
}

// round 5
// speedup vs baseline: 2.3477x; 1.0014x over previous
#include <cuda_runtime.h>
#include <math.h>

// ---------------- geometry ----------------
#define W_    2048
#define HOUT  2046                 // VALID 3x3 output dim
#define NTOT  (W_ * W_)

// warp-strip decomposition: thread = 2 cols (float2), warp = 64 input cols,
// 62 owned output cols. Strip 32 ends exactly at col 2048 -> no col clipping.
#define COLS_OUT 62
#define R_OUT  20
#define STRIPS 33                  // 33*62 = 2046 exactly
#define BANDS  103                 // ceil(2046/20)
#define NWARPS (STRIPS * BANDS)    // 3399
#define WPB    8                   // warps per block (256 threads)
#define NBLOCKS ((NWARPS + WPB - 1) / WPB)  // 425

__device__ float g_bpart[3 * NBLOCKS];
__device__ unsigned int g_count;   // zero at module load; reset by last block

struct RowState {
    float hE[2];    // horizontal 3-sum of E
    float hXX[2];   // horizontal 3-sum of sxx
    float hXY[2];   // horizontal 3-sum of sxy
    float syy[2];   // raw syy
    float sxy[2];   // raw sxy
};

__device__ __forceinline__ float warp_sum(float x) {
#pragma unroll
    for (int o = 16; o > 0; o >>= 1) x += __shfl_down_sync(0xffffffffu, x, o);
    return x;
}

// All loads unconditional: geometry guarantees in-bounds.
__device__ __forceinline__ void process_row(
    int r, int c0, int own_hi_c, bool ownrow,
    const float* __restrict__ pE, const float* __restrict__ pv,
    const float* __restrict__ ps, RowState& out, float& accE)
{
    const int base = r * W_ + c0;            // c0 even -> 8B-aligned float2
    const float2 E2  = *reinterpret_cast<const float2*>(pE + base);
    const float2 v2  = *reinterpret_cast<const float2*>(pv + base);
    const float2 s01 = *reinterpret_cast<const float2*>(ps + 3 * base);
    const float2 s23 = *reinterpret_cast<const float2*>(ps + 3 * base + 2);
    const float2 s45 = *reinterpret_cast<const float2*>(ps + 3 * base + 4);

    const float E[2]  = { E2.x, E2.y };
    const float v[2]  = { v2.x, v2.y };
    const float e0[2] = { s01.x, s23.y };
    const float e1[2] = { s01.y, s45.x };
    const float e2[2] = { s23.x, s45.y };

    float xx[2], xy[2];
#pragma unroll
    for (int k = 0; k < 2; k++) {
        const float frac = __fdividef(E[k], 1.0f - v[k] * v[k]);
        xx[k]      = (e0[k] + v[k] * e1[k]) * frac;
        out.syy[k] = (v[k] * e0[k] + e1[k]) * frac;
        xy[k]      = e2[k] * (1.0f - v[k]) * 0.5f * frac;
        out.sxy[k] = xy[k];
    }

    // horizontal 3-sums via neighbor-lane exchange (garbage at lane edges is
    // only consumed by excluded output positions p=0 / p=63)
    const float El = __shfl_up_sync  (0xffffffffu, E[1],  1);
    const float Er = __shfl_down_sync(0xffffffffu, E[0],  1);
    const float xl = __shfl_up_sync  (0xffffffffu, xx[1], 1);
    const float xr = __shfl_down_sync(0xffffffffu, xx[0], 1);
    const float yl = __shfl_up_sync  (0xffffffffu, xy[1], 1);
    const float yr = __shfl_down_sync(0xffffffffu, xy[0], 1);

    out.hE[0]  = El + E[0] + E[1];
    out.hE[1]  = E[0] + E[1] + Er;
    out.hXX[0] = xl + xx[0] + xx[1];
    out.hXX[1] = xx[0] + xx[1] + xr;
    out.hXY[0] = yl + xy[0] + xy[1];
    out.hXY[1] = xy[0] + xy[1] + yr;

    // mean(E): pixel owned iff its column < own_hi_c (coverage starts at cb)
    if (ownrow) {
        if (c0     < own_hi_c) accE += E[0];
        if (c0 + 1 < own_hi_c) accE += E[1];
    }
}

__global__ __launch_bounds__(256, 3)
void stress_loss_kernel(const float* __restrict__ pE,
                        const float* __restrict__ pv,
                        const float* __restrict__ ps,
                        float* __restrict__ out)
{
    const int wl   = threadIdx.x >> 5;
    const int w    = blockIdx.x * WPB + wl;
    const int lane = threadIdx.x & 31;
    const int tid  = threadIdx.x;
    float accx = 0.f, accy = 0.f, accE = 0.f;

    if (w < NWARPS) {
        const int strip = w / BANDS;
        const int band  = w - strip * BANDS;
        const int cb = strip * COLS_OUT;
        const int r0 = band * R_OUT;
        const int rows_out = min(R_OUT, HOUT - r0);
        const int c0 = cb + lane * 2;
        const int own_hi_c = (strip == STRIPS - 1) ? W_ : cb + COLS_OUT;
        const int own_hi_r = (band  == BANDS  - 1) ? W_ : r0 + R_OUT;
        // output validity: p = lane*2+k must be in [1, 63)
        const bool ok0 = (lane > 0);
        const bool ok1 = (lane < 31);

        RowState A, B, C;
        process_row(r0,     c0, own_hi_c, (r0     < own_hi_r), pE, pv, ps, A, accE);
        process_row(r0 + 1, c0, own_hi_c, (r0 + 1 < own_hi_r), pE, pv, ps, B, accE);

#pragma unroll 4
        for (int i = 0; i < rows_out; i++) {
            const int r = r0 + i + 2;
            process_row(r, c0, own_hi_c, (r < own_hi_r), pE, pv, ps, C, accE);

            float vxy[2], vyy[2], Ec[2];
#pragma unroll
            for (int k = 0; k < 2; k++) {
                vxy[k] = A.sxy[k] + B.sxy[k] + C.sxy[k];
                vyy[k] = A.syy[k] + B.syy[k] + C.syy[k];
                Ec[k]  = A.hE[k]  + B.hE[k]  + C.hE[k];
            }
            const float vxyl = __shfl_up_sync  (0xffffffffu, vxy[1], 1);
            const float vxyr = __shfl_down_sync(0xffffffffu, vxy[0], 1);
            const float vyyl = __shfl_up_sync  (0xffffffffu, vyy[1], 1);
            const float vyyr = __shfl_down_sync(0xffffffffu, vyy[0], 1);

            const float dxy[2] = { vxyl - vxy[1], vxy[0] - vxyr };
            const float dyy[2] = { vyyl - vyy[1], vyy[0] - vyyr };

            if (ok0) {
                const float fx = C.hXX[0] - A.hXX[0] + dxy[0];
                const float fy = dyy[0] + C.hXY[0] - A.hXY[0];
                const float inv = __fdividef(1.0f, Ec[0]);
                accx += fabsf(fx * inv);
                accy += fabsf(fy * inv);
            }
            if (ok1) {
                const float fx = C.hXX[1] - A.hXX[1] + dxy[1];
                const float fy = dyy[1] + C.hXY[1] - A.hXY[1];
                const float inv = __fdividef(1.0f, Ec[1]);
                accx += fabsf(fx * inv);
                accy += fabsf(fy * inv);
            }
            A = B; B = C;
        }
    }

    // ---- block reduction ----
    accx = warp_sum(accx);
    accy = warp_sum(accy);
    accE = warp_sum(accE);

    __shared__ float red[3][WPB];
    __shared__ int isLast;
    if (lane == 0) {
        red[0][wl] = accx;
        red[1][wl] = accy;
        red[2][wl] = accE;
    }
    __syncthreads();
    if (tid == 0) {
        float ax = 0.f, ay = 0.f, ae = 0.f;
#pragma unroll
        for (int q = 0; q < WPB; q++) { ax += red[0][q]; ay += red[1][q]; ae += red[2][q]; }
        g_bpart[blockIdx.x]               = ax;
        g_bpart[NBLOCKS + blockIdx.x]     = ay;
        g_bpart[2 * NBLOCKS + blockIdx.x] = ae;
        __threadfence();
        const unsigned int old = atomicAdd(&g_count, 1u);
        isLast = (old == NBLOCKS - 1);
    }
    __syncthreads();

    // ---- last block finalizes (fixed-order sum -> deterministic) ----
    if (isLast) {
        volatile const float* vp = (volatile const float*)g_bpart;
        double ax = 0.0, ay = 0.0, ae = 0.0;
        for (int i = tid; i < NBLOCKS; i += 256) {
            ax += (double)vp[i];
            ay += (double)vp[NBLOCKS + i];
            ae += (double)vp[2 * NBLOCKS + i];
        }
        __shared__ double sax[256], say[256], sae[256];
        sax[tid] = ax; say[tid] = ay; sae[tid] = ae;
        __syncthreads();
        for (int s = 128; s > 0; s >>= 1) {
            if (tid < s) { sax[tid] += sax[tid + s]; say[tid] += say[tid + s]; sae[tid] += sae[tid + s]; }
            __syncthreads();
        }
        if (tid == 0) {
            const double M = (double)HOUT * (double)HOUT;
            out[0] = (float)(sax[0] / M + say[0] / M
                             + fabs(sae[0] / (double)NTOT - 1.0) / 100.0);
            g_count = 0;   // reset for next graph replay
        }
    }
}

extern "C" void kernel_launch(void* const* d_in, const int* in_sizes, int n_in,
                              void* d_out, int out_size)
{
    const float* pred_E = (const float*)d_in[0];
    const float* pred_v = (const float*)d_in[1];
    const float* strain = (const float*)d_in[2];
    float* out = (float*)d_out;

    stress_loss_kernel<<<NBLOCKS, 256>>>(pred_E, pred_v, strain, out);
}